// round 1
// baseline (speedup 1.0000x reference)
#include <cuda_runtime.h>
#include <math_constants.h>

// Problem dims (fixed instance)
#define BQ  4
#define FQ  256
#define TQ  60000
#define NBQ 8
#define FB  32
#define ND  5
#define NLA 11
#define NG  15
#define EPSQ 1e-8f

#define TT1 1024   // time tile for K1
#define TT2 1024   // time tile for K2/K3

// ---- scratch (static device arrays; no allocation) ----
__device__ float g_xp[BQ * NBQ * TQ];   // pooled band envelopes  [B, NB, T]
__device__ float g_xg[BQ * TQ];         // smoothed flux (pre-norm)
__device__ float g_fs[BQ * TQ];         // fused pre-sigmoid
__device__ float g_maxxg[BQ];
__device__ float g_maxfs[BQ];

__device__ __forceinline__ void atomicMaxFloatSigned(float* addr, float val) {
    int* ia = (int*)addr;
    int old = *ia;
    while (__int_as_float(old) < val) {
        int assumed = old;
        old = atomicCAS(ia, assumed, __float_as_int(val));
        if (old == assumed) break;
    }
}

__global__ void k0_init() {
    int i = threadIdx.x;
    if (i < BQ) { g_maxxg[i] = 0.0f; g_maxfs[i] = -CUDART_INF_F; }
}

// ============================================================================
// K1: x [B,F,T] -> xp [B,NB,T]
//   xl = log1p(exp(log_gamma)*x); xd = depthwise 5-tap temporal conv + b;
//   xp = sum_f relu(xd)  over the 32 freq rows of each band.
// HBM-bound: reads 245.8 MB once. Logs computed once per element into smem.
// ============================================================================
__global__ __launch_bounds__(256) void k1_xp(
    const float* __restrict__ x,
    const float* __restrict__ log_gamma,
    const float* __restrict__ diff_w,
    const float* __restrict__ diff_b)
{
    __shared__ __align__(16) float sxl[TT1 + 4];

    const int tile = blockIdx.x;
    const int band = blockIdx.y;
    const int b    = blockIdx.z;
    const int t0   = tile * TT1;
    const int tid  = threadIdx.x;

    const float gamma = __expf(log_gamma[band]);
    float dw[ND];
#pragma unroll
    for (int k = 0; k < ND; ++k) dw[k] = diff_w[band * ND + k];
    const float db = diff_b[band];

    float acc[4] = {0.f, 0.f, 0.f, 0.f};

    const float* xb = x + ((size_t)b * FQ + (size_t)band * FB) * TQ;

    for (int f = 0; f < FB; ++f) {
        const float* row = xb + (size_t)f * TQ;
        // load tile + 2-halo each side, compute log once per element
        for (int i = tid; i < TT1 + 4; i += 256) {
            int t = t0 - 2 + i;
            float v = 0.0f;
            if (t >= 0 && t < TQ) v = __logf(fmaf(gamma, row[t], 1.0f));
            sxl[i] = v;
        }
        __syncthreads();

        float4 a = *(const float4*)&sxl[4 * tid];
        float4 c = *(const float4*)&sxl[4 * tid + 4];
        float v[8] = {a.x, a.y, a.z, a.w, c.x, c.y, c.z, c.w};
#pragma unroll
        for (int j = 0; j < 4; ++j) {
            float s = db;
#pragma unroll
            for (int k = 0; k < ND; ++k) s = fmaf(dw[k], v[j + k], s);
            acc[j] += fmaxf(s, 0.0f);
        }
        __syncthreads();
    }

    float* out = g_xp + ((size_t)b * NBQ + band) * TQ;
    int t = t0 + 4 * tid;
    if (t + 3 < TQ) {
        *(float4*)&out[t] = make_float4(acc[0], acc[1], acc[2], acc[3]);
    } else {
#pragma unroll
        for (int j = 0; j < 4; ++j)
            if (t + j < TQ) out[t + j] = acc[j];
    }
}

// ============================================================================
// K2: xp [B,NB,T] -> xg [B,T] (+ per-batch max, nonneg -> int atomicMax)
//   xs = xp - (dwconv11(xp) + la_b); xm = sum_band mix_w*xs;
//   xg = relu(conv15_gauss(xm) + g_b)
// ============================================================================
#define H2 12  // 7 (gauss) + 5 (moving avg) halo
__global__ __launch_bounds__(256) void k2_xg(
    const float* __restrict__ la_w, const float* __restrict__ la_b,
    const float* __restrict__ mix_w,
    const float* __restrict__ g_w,  const float* __restrict__ g_b)
{
    __shared__ float sxp[NBQ][TT2 + 2 * H2];
    __shared__ float sxm[TT2 + 14];
    __shared__ float wlaw[NBQ * NLA], wg[NG], wlab[NBQ], wmw[NBQ];

    const int tile = blockIdx.x;
    const int b    = blockIdx.y;
    const int t0   = tile * TT2;
    const int tid  = threadIdx.x;

    if (tid < NBQ * NLA) wlaw[tid] = la_w[tid];
    if (tid < NG)        wg[tid]   = g_w[tid];
    if (tid < NBQ)       { wlab[tid] = la_b[tid]; wmw[tid] = mix_w[tid]; }

    for (int band = 0; band < NBQ; ++band) {
        const float* src = g_xp + ((size_t)b * NBQ + band) * TQ;
        for (int i = tid; i < TT2 + 2 * H2; i += 256) {
            int t = t0 - H2 + i;
            sxp[band][i] = (t >= 0 && t < TQ) ? src[t] : 0.0f;
        }
    }
    __syncthreads();

    // xm over [t0-7, t0+TT2+7)
    for (int i = tid; i < TT2 + 14; i += 256) {
        int t = t0 - 7 + i;
        float xm = 0.0f;
        if (t >= 0 && t < TQ) {
#pragma unroll
            for (int band = 0; band < NBQ; ++band) {
                float conv = wlab[band];
#pragma unroll
                for (int j = 0; j < NLA; ++j)
                    conv = fmaf(wlaw[band * NLA + j], sxp[band][i + j], conv);
                xm = fmaf(wmw[band], sxp[band][i + 5] - conv, xm);
            }
        }
        sxm[i] = xm;
    }
    __syncthreads();

    const float gb = g_b[0];
    float lmax = 0.0f;
    for (int i = tid; i < TT2; i += 256) {
        int t = t0 + i;
        if (t < TQ) {
            float s = gb;
#pragma unroll
            for (int k = 0; k < NG; ++k) s = fmaf(wg[k], sxm[i + k], s);
            s = fmaxf(s, 0.0f);
            g_xg[(size_t)b * TQ + t] = s;
            lmax = fmaxf(lmax, s);
        }
    }
#pragma unroll
    for (int off = 16; off; off >>= 1)
        lmax = fmaxf(lmax, __shfl_xor_sync(0xffffffffu, lmax, off));
    if ((tid & 31) == 0)
        atomicMax((int*)&g_maxxg[b], __float_as_int(lmax));  // values >= 0
}

// ============================================================================
// K3: sf = xg / (max_xg + eps)  -> d_out[0 .. B*T)
//     fm = S*sf + cb (S = sum fc_w, cb = fc_b); fs = conv15(fm, fg_w) + fg_b
//     (zero padding on fm outside [0,T)); per-batch signed max of fs.
// ============================================================================
__global__ __launch_bounds__(256) void k3_fs(
    const float* __restrict__ fc_w, const float* __restrict__ fc_b,
    const float* __restrict__ fg_w, const float* __restrict__ fg_b,
    float* __restrict__ out_sf)
{
    __shared__ float sfm[TT2 + 14];
    __shared__ float wfg[NG];

    const int tile = blockIdx.x;
    const int b    = blockIdx.y;
    const int t0   = tile * TT2;
    const int tid  = threadIdx.x;

    if (tid < NG) wfg[tid] = fg_w[tid];
    const float S  = fc_w[0] + fc_w[1] + fc_w[2] + fc_w[3];
    const float cb = fc_b[0];
    const float inv = 1.0f / (g_maxxg[b] + EPSQ);
    const float* xg = g_xg + (size_t)b * TQ;

    for (int i = tid; i < TT2 + 14; i += 256) {
        int t = t0 - 7 + i;
        float v = 0.0f;
        if (t >= 0 && t < TQ) {
            float sf = xg[t] * inv;
            if (i >= 7 && i < TT2 + 7)                 // tile-owned t only
                out_sf[(size_t)b * TQ + t] = sf;
            v = fmaf(S, sf, cb);
        }
        sfm[i] = v;
    }
    __syncthreads();

    const float fgb = fg_b[0];
    float lmax = -CUDART_INF_F;
    for (int i = tid; i < TT2; i += 256) {
        int t = t0 + i;
        if (t < TQ) {
            float s = fgb;
#pragma unroll
            for (int k = 0; k < NG; ++k) s = fmaf(wfg[k], sfm[i + k], s);
            g_fs[(size_t)b * TQ + t] = s;
            lmax = fmaxf(lmax, s);
        }
    }
#pragma unroll
    for (int off = 16; off; off >>= 1)
        lmax = fmaxf(lmax, __shfl_xor_sync(0xffffffffu, lmax, off));
    if ((tid & 31) == 0)
        atomicMaxFloatSigned(&g_maxfs[b], lmax);
}

// ============================================================================
// K4: fused = sigmoid(fs) / (sigmoid(max fs) + eps)   (sigmoid is monotone)
// ============================================================================
__global__ __launch_bounds__(256) void k4_out(float* __restrict__ out2)
{
    const int b = blockIdx.y;
    const int t = blockIdx.x * 256 + threadIdx.x;
    if (t < TQ) {
        float m  = g_maxfs[b];
        float dn = 1.0f / (1.0f + __expf(-m));        // sigmoid(max fs)
        float fa = 1.0f / (1.0f + __expf(-g_fs[(size_t)b * TQ + t]));
        out2[(size_t)b * TQ + t] = fa / (dn + EPSQ);
    }
}

// ============================================================================
extern "C" void kernel_launch(void* const* d_in, const int* in_sizes, int n_in,
                              void* d_out, int out_size)
{
    const float* x         = (const float*)d_in[0];
    const float* log_gamma = (const float*)d_in[1];
    const float* diff_w    = (const float*)d_in[2];
    const float* diff_b    = (const float*)d_in[3];
    const float* la_w      = (const float*)d_in[4];
    const float* la_b      = (const float*)d_in[5];
    const float* mix_w     = (const float*)d_in[6];
    const float* g_w       = (const float*)d_in[7];
    const float* g_b       = (const float*)d_in[8];
    const float* fc_w      = (const float*)d_in[9];
    const float* fc_b      = (const float*)d_in[10];
    const float* fg_w      = (const float*)d_in[11];
    const float* fg_b      = (const float*)d_in[12];
    float* out = (float*)d_out;

    k0_init<<<1, 32>>>();

    dim3 g1((TQ + TT1 - 1) / TT1, NBQ, BQ);
    k1_xp<<<g1, 256>>>(x, log_gamma, diff_w, diff_b);

    dim3 g2((TQ + TT2 - 1) / TT2, BQ);
    k2_xg<<<g2, 256>>>(la_w, la_b, mix_w, g_w, g_b);
    k3_fs<<<g2, 256>>>(fc_w, fc_b, fg_w, fg_b, out);

    dim3 g4((TQ + 255) / 256, BQ);
    k4_out<<<g4, 256>>>(out + (size_t)BQ * TQ);
}

// round 2
// speedup vs baseline: 1.7438x; 1.7438x over previous
#include <cuda_runtime.h>
#include <math_constants.h>

// Problem dims (fixed instance)
#define BQ  4
#define FQ  256
#define TQ  60000
#define NBQ 8
#define FB  32
#define ND  5
#define NLA 11
#define NG  15
#define EPSQ 1e-8f

#define TT2 256    // time tile for K2/K3 (one output point per thread)
#define H2  12     // k2 halo: 5 (moving-avg) + 7 (gauss)

// ---- scratch (static device arrays; no allocation) ----
__device__ float g_xp[BQ * NBQ * TQ];   // pooled band envelopes  [B, NB, T]
__device__ float g_xg[BQ * TQ];         // smoothed flux (pre-norm)
__device__ float g_fs[BQ * TQ];         // fused pre-sigmoid
__device__ float g_maxxg[BQ];
__device__ float g_maxfs[BQ];

__device__ __forceinline__ void atomicMaxFloatSigned(float* addr, float val) {
    int* ia = (int*)addr;
    int old = *ia;
    while (__int_as_float(old) < val) {
        int assumed = old;
        old = atomicCAS(ia, assumed, __float_as_int(val));
        if (old == assumed) break;
    }
}

// ============================================================================
// K1: x [B,F,T] -> xp [B,NB,T]   (barrier-free, warp-autonomous)
//   Each warp owns a 128-t chunk of one (b, band). Lane owns 4 consecutive t.
//   Per freq row: one float4 LDG, 4 logs, halo via shuffles, 5-tap conv,
//   relu, accumulate over the 32 rows of the band. No smem, no syncthreads.
// ============================================================================
__global__ __launch_bounds__(256) void k1_xp(
    const float* __restrict__ x,
    const float* __restrict__ log_gamma,
    const float* __restrict__ diff_w,
    const float* __restrict__ diff_b)
{
    const int tid  = threadIdx.x;
    // fold max-init here (k2/k3 read these only after k1 completes)
    if (blockIdx.x == 0 && blockIdx.y == 0 && blockIdx.z == 0 && tid < BQ) {
        g_maxxg[tid] = 0.0f;
        g_maxfs[tid] = -CUDART_INF_F;
    }

    const int warp = tid >> 5;
    const int lane = tid & 31;
    const int band = blockIdx.y;
    const int b    = blockIdx.z;
    const int tbase = (blockIdx.x * 8 + warp) * 128 + 4 * lane;
    const bool inr  = (tbase < TQ);   // TQ % 4 == 0 -> full float4 in range

    const float gamma = __expf(log_gamma[band]);
    const float dw0 = diff_w[band * ND + 0];
    const float dw1 = diff_w[band * ND + 1];
    const float dw2 = diff_w[band * ND + 2];
    const float dw3 = diff_w[band * ND + 3];
    const float dw4 = diff_w[band * ND + 4];
    const float db  = diff_b[band];

    const float* xb = x + ((size_t)b * FQ + (size_t)band * FB) * TQ;

    float acc0 = 0.f, acc1 = 0.f, acc2 = 0.f, acc3 = 0.f;

#pragma unroll 4
    for (int f = 0; f < FB; ++f) {
        const float* row = xb + (size_t)f * TQ;
        float l0 = 0.f, l1 = 0.f, l2 = 0.f, l3 = 0.f;
        if (inr) {
            float4 v = *(const float4*)(row + tbase);
            l0 = __logf(fmaf(gamma, v.x, 1.0f));
            l1 = __logf(fmaf(gamma, v.y, 1.0f));
            l2 = __logf(fmaf(gamma, v.z, 1.0f));
            l3 = __logf(fmaf(gamma, v.w, 1.0f));
        }
        // halo via shuffles (out-of-range lanes carry 0 == zero padding of xl)
        float lm2 = __shfl_up_sync(0xffffffffu, l2, 1);
        float lm1 = __shfl_up_sync(0xffffffffu, l3, 1);
        float lp4 = __shfl_down_sync(0xffffffffu, l0, 1);
        float lp5 = __shfl_down_sync(0xffffffffu, l1, 1);
        if (lane == 0) {
            lm2 = (tbase >= 2) ? __logf(fmaf(gamma, row[tbase - 2], 1.0f)) : 0.f;
            lm1 = (tbase >= 1) ? __logf(fmaf(gamma, row[tbase - 1], 1.0f)) : 0.f;
        }
        if (lane == 31) {
            lp4 = (tbase + 4 < TQ) ? __logf(fmaf(gamma, row[tbase + 4], 1.0f)) : 0.f;
            lp5 = (tbase + 5 < TQ) ? __logf(fmaf(gamma, row[tbase + 5], 1.0f)) : 0.f;
        }
        float s;
        s = db; s = fmaf(dw0, lm2, s); s = fmaf(dw1, lm1, s); s = fmaf(dw2, l0, s);
                s = fmaf(dw3, l1, s);  s = fmaf(dw4, l2, s);  acc0 += fmaxf(s, 0.f);
        s = db; s = fmaf(dw0, lm1, s); s = fmaf(dw1, l0, s);  s = fmaf(dw2, l1, s);
                s = fmaf(dw3, l2, s);  s = fmaf(dw4, l3, s);  acc1 += fmaxf(s, 0.f);
        s = db; s = fmaf(dw0, l0, s);  s = fmaf(dw1, l1, s);  s = fmaf(dw2, l2, s);
                s = fmaf(dw3, l3, s);  s = fmaf(dw4, lp4, s); acc2 += fmaxf(s, 0.f);
        s = db; s = fmaf(dw0, l1, s);  s = fmaf(dw1, l2, s);  s = fmaf(dw2, l3, s);
                s = fmaf(dw3, lp4, s); s = fmaf(dw4, lp5, s); acc3 += fmaxf(s, 0.f);
    }

    if (inr) {
        float* out = g_xp + ((size_t)b * NBQ + band) * TQ + tbase;
        *(float4*)out = make_float4(acc0, acc1, acc2, acc3);
    }
}

// ============================================================================
// K2: xp [B,NB,T] -> xg [B,T] (+ per-batch nonneg max via int atomicMax)
//   xs = xp - (dwconv11(xp) + la_b); xm = sum_band mix_w*xs;
//   xg = relu(conv15_gauss(xm) + g_b).  One output point per thread.
// ============================================================================
__global__ __launch_bounds__(256) void k2_xg(
    const float* __restrict__ la_w, const float* __restrict__ la_b,
    const float* __restrict__ mix_w,
    const float* __restrict__ g_w,  const float* __restrict__ g_b)
{
    __shared__ float sxp[NBQ][TT2 + 2 * H2];   // 8 x 280
    __shared__ float sxm[TT2 + 14];            // 270
    __shared__ float wlaw[NBQ * NLA], wg[NG], wlab[NBQ], wmw[NBQ];

    const int t0  = blockIdx.x * TT2;
    const int b   = blockIdx.y;
    const int tid = threadIdx.x;

    if (tid < NBQ * NLA) wlaw[tid] = la_w[tid];
    if (tid < NG)        wg[tid]   = g_w[tid];
    if (tid < NBQ)       { wlab[tid] = la_b[tid]; wmw[tid] = mix_w[tid]; }

    const int W2 = TT2 + 2 * H2;  // 280
    for (int n = tid; n < NBQ * W2; n += 256) {
        int band = n / W2;
        int i    = n - band * W2;
        int t    = t0 - H2 + i;
        sxp[band][i] = (t >= 0 && t < TQ)
                     ? g_xp[((size_t)b * NBQ + band) * TQ + t] : 0.0f;
    }
    __syncthreads();

    // xm over [t0-7, t0+TT2+7)
    for (int i = tid; i < TT2 + 14; i += 256) {
        int t = t0 - 7 + i;
        float xm = 0.0f;
        if (t >= 0 && t < TQ) {
#pragma unroll
            for (int band = 0; band < NBQ; ++band) {
                float conv = wlab[band];
#pragma unroll
                for (int j = 0; j < NLA; ++j)
                    conv = fmaf(wlaw[band * NLA + j], sxp[band][i + j], conv);
                xm = fmaf(wmw[band], sxp[band][i + 5] - conv, xm);
            }
        }
        sxm[i] = xm;
    }
    __syncthreads();

    const float gb = g_b[0];
    float lmax = 0.0f;
    {
        int t = t0 + tid;
        if (t < TQ) {
            float s = gb;
#pragma unroll
            for (int k = 0; k < NG; ++k) s = fmaf(wg[k], sxm[tid + k], s);
            s = fmaxf(s, 0.0f);
            g_xg[(size_t)b * TQ + t] = s;
            lmax = s;
        }
    }
#pragma unroll
    for (int off = 16; off; off >>= 1)
        lmax = fmaxf(lmax, __shfl_xor_sync(0xffffffffu, lmax, off));
    if ((tid & 31) == 0)
        atomicMax((int*)&g_maxxg[b], __float_as_int(lmax));  // values >= 0
}

// ============================================================================
// K3: sf = xg / (max_xg + eps)  -> d_out[0 .. B*T)
//     fm = S*sf + cb (S = sum fc_w, cb = fc_b); fs = conv15(fm, fg_w) + fg_b
//     (zero padding on fm outside [0,T)); per-batch signed max of fs.
// ============================================================================
__global__ __launch_bounds__(256) void k3_fs(
    const float* __restrict__ fc_w, const float* __restrict__ fc_b,
    const float* __restrict__ fg_w, const float* __restrict__ fg_b,
    float* __restrict__ out_sf)
{
    __shared__ float sfm[TT2 + 14];
    __shared__ float wfg[NG];

    const int t0  = blockIdx.x * TT2;
    const int b   = blockIdx.y;
    const int tid = threadIdx.x;

    if (tid < NG) wfg[tid] = fg_w[tid];
    const float S   = fc_w[0] + fc_w[1] + fc_w[2] + fc_w[3];
    const float cb  = fc_b[0];
    const float inv = 1.0f / (g_maxxg[b] + EPSQ);
    const float* xg = g_xg + (size_t)b * TQ;

    for (int i = tid; i < TT2 + 14; i += 256) {
        int t = t0 - 7 + i;
        float v = 0.0f;
        if (t >= 0 && t < TQ) {
            float sf = xg[t] * inv;
            if (i >= 7 && i < TT2 + 7)                 // tile-owned t only
                out_sf[(size_t)b * TQ + t] = sf;
            v = fmaf(S, sf, cb);
        }
        sfm[i] = v;
    }
    __syncthreads();

    const float fgb = fg_b[0];
    float lmax = -CUDART_INF_F;
    {
        int t = t0 + tid;
        if (t < TQ) {
            float s = fgb;
#pragma unroll
            for (int k = 0; k < NG; ++k) s = fmaf(wfg[k], sfm[tid + k], s);
            g_fs[(size_t)b * TQ + t] = s;
            lmax = s;
        }
    }
#pragma unroll
    for (int off = 16; off; off >>= 1)
        lmax = fmaxf(lmax, __shfl_xor_sync(0xffffffffu, lmax, off));
    if ((tid & 31) == 0)
        atomicMaxFloatSigned(&g_maxfs[b], lmax);
}

// ============================================================================
// K4: fused = sigmoid(fs) / (sigmoid(max fs) + eps)   (sigmoid is monotone)
// ============================================================================
__global__ __launch_bounds__(256) void k4_out(float* __restrict__ out2)
{
    const int b = blockIdx.y;
    const int t = blockIdx.x * 256 + threadIdx.x;
    if (t < TQ) {
        float m  = g_maxfs[b];
        float dn = 1.0f / (1.0f + __expf(-m));        // sigmoid(max fs)
        float fa = 1.0f / (1.0f + __expf(-g_fs[(size_t)b * TQ + t]));
        out2[(size_t)b * TQ + t] = fa / (dn + EPSQ);
    }
}

// ============================================================================
extern "C" void kernel_launch(void* const* d_in, const int* in_sizes, int n_in,
                              void* d_out, int out_size)
{
    const float* x         = (const float*)d_in[0];
    const float* log_gamma = (const float*)d_in[1];
    const float* diff_w    = (const float*)d_in[2];
    const float* diff_b    = (const float*)d_in[3];
    const float* la_w      = (const float*)d_in[4];
    const float* la_b      = (const float*)d_in[5];
    const float* mix_w     = (const float*)d_in[6];
    const float* g_w       = (const float*)d_in[7];
    const float* g_b       = (const float*)d_in[8];
    const float* fc_w      = (const float*)d_in[9];
    const float* fc_b      = (const float*)d_in[10];
    const float* fg_w      = (const float*)d_in[11];
    const float* fg_b      = (const float*)d_in[12];
    float* out = (float*)d_out;

    dim3 g1((TQ + 1023) / 1024, NBQ, BQ);      // 59 x 8 x 4
    k1_xp<<<g1, 256>>>(x, log_gamma, diff_w, diff_b);

    dim3 g2((TQ + TT2 - 1) / TT2, BQ);         // 235 x 4
    k2_xg<<<g2, 256>>>(la_w, la_b, mix_w, g_w, g_b);
    k3_fs<<<g2, 256>>>(fc_w, fc_b, fg_w, fg_b, out);

    dim3 g4((TQ + 255) / 256, BQ);
    k4_out<<<g4, 256>>>(out + (size_t)BQ * TQ);
}

// round 3
// speedup vs baseline: 1.8056x; 1.0355x over previous
#include <cuda_runtime.h>
#include <math_constants.h>

// Problem dims (fixed instance)
#define BQ  4
#define FQ  256
#define TQ  60000
#define NBQ 8
#define FB  32
#define ND  5
#define NLA 11
#define NG  15
#define EPSQ 1e-8f

#define TT2 256    // tail tile (one output point per thread)
#define H2  12     // k2 halo: 5 (moving-avg) + 7 (gauss)
#define TAILBLOCKS 592   // 4 per SM, guaranteed co-resident for grid barrier

// ---- scratch (static device arrays; no allocation) ----
__device__ float g_xp[BQ * NBQ * TQ];   // pooled band envelopes  [B, NB, T]
__device__ float g_xg[BQ * TQ];         // smoothed flux (pre-norm)
__device__ float g_fs[BQ * TQ];         // fused pre-sigmoid
__device__ float g_maxxg[BQ];
__device__ float g_maxfs[BQ];

__device__ volatile unsigned g_gen = 0;
__device__ unsigned g_count = 0;

__device__ __forceinline__ void atomicMaxFloatSigned(float* addr, float val) {
    int* ia = (int*)addr;
    int old = *ia;
    while (__int_as_float(old) < val) {
        int assumed = old;
        old = atomicCAS(ia, assumed, __float_as_int(val));
        if (old == assumed) break;
    }
}

// generation-counter grid barrier; all TAILBLOCKS blocks are co-resident.
__device__ __forceinline__ void grid_barrier() {
    __syncthreads();
    if (threadIdx.x == 0) {
        __threadfence();
        unsigned my = g_gen;
        if (atomicAdd(&g_count, 1) == TAILBLOCKS - 1) {
            g_count = 0;
            __threadfence();
            g_gen = my + 1;
        } else {
            while (g_gen == my) { __nanosleep(32); }
        }
    }
    __syncthreads();
}

// ============================================================================
// K1: x [B,F,T] -> xp [B,NB,T]   (barrier-free, warp-autonomous, 8 t/lane)
//   Warp owns a 256-t chunk of one (b, band); lane owns 8 consecutive t.
//   Per freq row: 2 streaming float4 LDGs, 8 logs, halo via 4 shuffles,
//   5-tap conv, relu, accumulate over the 32 rows. No smem, no barriers.
// ============================================================================
__global__ __launch_bounds__(256) void k1_xp(
    const float* __restrict__ x,
    const float* __restrict__ log_gamma,
    const float* __restrict__ diff_w,
    const float* __restrict__ diff_b)
{
    const int tid = threadIdx.x;
    // fold max-init here (tail reads these only after k1 completes)
    if (blockIdx.x == 0 && blockIdx.y == 0 && blockIdx.z == 0 && tid < BQ) {
        g_maxxg[tid] = 0.0f;
        g_maxfs[tid] = -CUDART_INF_F;
    }

    const int warp = tid >> 5;
    const int lane = tid & 31;
    const int band = blockIdx.y;
    const int b    = blockIdx.z;
    const int tbase = (blockIdx.x * 8 + warp) * 256 + 8 * lane;
    const bool inr  = (tbase < TQ);   // TQ % 8 == 0 -> full 8 in range

    const float gamma = __expf(log_gamma[band]);
    const float dw0 = diff_w[band * ND + 0];
    const float dw1 = diff_w[band * ND + 1];
    const float dw2 = diff_w[band * ND + 2];
    const float dw3 = diff_w[band * ND + 3];
    const float dw4 = diff_w[band * ND + 4];
    const float db  = diff_b[band];

    const float* xb = x + ((size_t)b * FQ + (size_t)band * FB) * TQ;

    float acc[8];
#pragma unroll
    for (int j = 0; j < 8; ++j) acc[j] = 0.f;

#pragma unroll 2
    for (int f = 0; f < FB; ++f) {
        const float* row = xb + (size_t)f * TQ;
        float e[12];   // l[-2..9] window
        if (inr) {
            float4 v0 = __ldcs((const float4*)(row + tbase));
            float4 v1 = __ldcs((const float4*)(row + tbase + 4));
            e[2]  = __logf(fmaf(gamma, v0.x, 1.0f));
            e[3]  = __logf(fmaf(gamma, v0.y, 1.0f));
            e[4]  = __logf(fmaf(gamma, v0.z, 1.0f));
            e[5]  = __logf(fmaf(gamma, v0.w, 1.0f));
            e[6]  = __logf(fmaf(gamma, v1.x, 1.0f));
            e[7]  = __logf(fmaf(gamma, v1.y, 1.0f));
            e[8]  = __logf(fmaf(gamma, v1.z, 1.0f));
            e[9]  = __logf(fmaf(gamma, v1.w, 1.0f));
        } else {
#pragma unroll
            for (int j = 2; j < 10; ++j) e[j] = 0.f;
        }
        // halo via shuffles (out-of-range lanes carry 0 == zero padding)
        e[0]  = __shfl_up_sync(0xffffffffu, e[8], 1);
        e[1]  = __shfl_up_sync(0xffffffffu, e[9], 1);
        e[10] = __shfl_down_sync(0xffffffffu, e[2], 1);
        e[11] = __shfl_down_sync(0xffffffffu, e[3], 1);
        if (lane == 0) {
            e[0] = (tbase >= 2) ? __logf(fmaf(gamma, row[tbase - 2], 1.0f)) : 0.f;
            e[1] = (tbase >= 1) ? __logf(fmaf(gamma, row[tbase - 1], 1.0f)) : 0.f;
        }
        if (lane == 31 && inr) {
            e[10] = (tbase + 8 < TQ) ? __logf(fmaf(gamma, row[tbase + 8], 1.0f)) : 0.f;
            e[11] = (tbase + 9 < TQ) ? __logf(fmaf(gamma, row[tbase + 9], 1.0f)) : 0.f;
        }
#pragma unroll
        for (int j = 0; j < 8; ++j) {
            float s = db;
            s = fmaf(dw0, e[j],     s);
            s = fmaf(dw1, e[j + 1], s);
            s = fmaf(dw2, e[j + 2], s);
            s = fmaf(dw3, e[j + 3], s);
            s = fmaf(dw4, e[j + 4], s);
            acc[j] += fmaxf(s, 0.f);
        }
    }

    if (inr) {
        float* out = g_xp + ((size_t)b * NBQ + band) * TQ + tbase;
        *(float4*)(out)     = make_float4(acc[0], acc[1], acc[2], acc[3]);
        *(float4*)(out + 4) = make_float4(acc[4], acc[5], acc[6], acc[7]);
    }
}

// ============================================================================
// TAIL: single persistent kernel, 3 phases split by grid barriers.
//  Phase A (k2): xp -> xg + per-batch max(xg)
//  Phase B (k3): sf = xg/(max+eps) -> out; fs = conv15(S*sf+cb) + fgb; max(fs)
//  Phase C (k4): fused = sigmoid(fs)/(sigmoid(max fs)+eps)
// ============================================================================
#define NTILE ((TQ + TT2 - 1) / TT2)     // 235
#define NJOBS (NTILE * BQ)               // 940

__global__ __launch_bounds__(256, 4) void k_tail(
    const float* __restrict__ la_w, const float* __restrict__ la_b,
    const float* __restrict__ mix_w,
    const float* __restrict__ g_w,  const float* __restrict__ g_b,
    const float* __restrict__ fc_w, const float* __restrict__ fc_b,
    const float* __restrict__ fg_w, const float* __restrict__ fg_b,
    float* __restrict__ out_sf, float* __restrict__ out_fn)
{
    __shared__ float sxp[NBQ][TT2 + 2 * H2];   // 8 x 280
    __shared__ float sxm[TT2 + 14];            // reused as sfm in phase B
    __shared__ float wlaw[NBQ * NLA], wg[NG], wfg[NG], wlab[NBQ], wmw[NBQ];

    const int tid = threadIdx.x;
    if (tid < NBQ * NLA) wlaw[tid] = la_w[tid];
    if (tid < NG)        { wg[tid] = g_w[tid]; wfg[tid] = fg_w[tid]; }
    if (tid < NBQ)       { wlab[tid] = la_b[tid]; wmw[tid] = mix_w[tid]; }
    __syncthreads();

    // ---------------- Phase A: k2 ----------------
    const float gb = g_b[0];
    for (int job = blockIdx.x; job < NJOBS; job += TAILBLOCKS) {
        const int b  = job / NTILE;
        const int t0 = (job - b * NTILE) * TT2;

        const int W2 = TT2 + 2 * H2;  // 280
        for (int n = tid; n < NBQ * W2; n += 256) {
            int band = n / W2;
            int i    = n - band * W2;
            int t    = t0 - H2 + i;
            sxp[band][i] = (t >= 0 && t < TQ)
                         ? g_xp[((size_t)b * NBQ + band) * TQ + t] : 0.0f;
        }
        __syncthreads();

        for (int i = tid; i < TT2 + 14; i += 256) {
            int t = t0 - 7 + i;
            float xm = 0.0f;
            if (t >= 0 && t < TQ) {
#pragma unroll
                for (int band = 0; band < NBQ; ++band) {
                    float conv = wlab[band];
#pragma unroll
                    for (int j = 0; j < NLA; ++j)
                        conv = fmaf(wlaw[band * NLA + j], sxp[band][i + j], conv);
                    xm = fmaf(wmw[band], sxp[band][i + 5] - conv, xm);
                }
            }
            sxm[i] = xm;
        }
        __syncthreads();

        float lmax = 0.0f;
        {
            int t = t0 + tid;
            if (t < TQ) {
                float s = gb;
#pragma unroll
                for (int k = 0; k < NG; ++k) s = fmaf(wg[k], sxm[tid + k], s);
                s = fmaxf(s, 0.0f);
                g_xg[(size_t)b * TQ + t] = s;
                lmax = s;
            }
        }
#pragma unroll
        for (int off = 16; off; off >>= 1)
            lmax = fmaxf(lmax, __shfl_xor_sync(0xffffffffu, lmax, off));
        if ((tid & 31) == 0)
            atomicMax((int*)&g_maxxg[b], __float_as_int(lmax));  // xg >= 0
        __syncthreads();
    }

    grid_barrier();

    // ---------------- Phase B: k3 ----------------
    const float S   = fc_w[0] + fc_w[1] + fc_w[2] + fc_w[3];
    const float cb  = fc_b[0];
    const float fgb = fg_b[0];
    float invb[BQ];
#pragma unroll
    for (int i = 0; i < BQ; ++i)
        invb[i] = 1.0f / (__ldcg(&g_maxxg[i]) + EPSQ);

    for (int job = blockIdx.x; job < NJOBS; job += TAILBLOCKS) {
        const int b  = job / NTILE;
        const int t0 = (job - b * NTILE) * TT2;
        const float inv = invb[b];
        const float* xg = g_xg + (size_t)b * TQ;

        for (int i = tid; i < TT2 + 14; i += 256) {
            int t = t0 - 7 + i;
            float v = 0.0f;
            if (t >= 0 && t < TQ) {
                float sf = xg[t] * inv;
                if (i >= 7 && i < TT2 + 7)             // tile-owned t only
                    out_sf[(size_t)b * TQ + t] = sf;
                v = fmaf(S, sf, cb);
            }
            sxm[i] = v;   // sfm
        }
        __syncthreads();

        float lmax = -CUDART_INF_F;
        {
            int t = t0 + tid;
            if (t < TQ) {
                float s = fgb;
#pragma unroll
                for (int k = 0; k < NG; ++k) s = fmaf(wfg[k], sxm[tid + k], s);
                g_fs[(size_t)b * TQ + t] = s;
                lmax = s;
            }
        }
#pragma unroll
        for (int off = 16; off; off >>= 1)
            lmax = fmaxf(lmax, __shfl_xor_sync(0xffffffffu, lmax, off));
        if ((tid & 31) == 0)
            atomicMaxFloatSigned(&g_maxfs[b], lmax);
        __syncthreads();
    }

    grid_barrier();

    // ---------------- Phase C: k4 ----------------
    float dnb[BQ];
#pragma unroll
    for (int i = 0; i < BQ; ++i) {
        float m = __ldcg(&g_maxfs[i]);
        dnb[i] = 1.0f / (1.0f / (1.0f + __expf(-m)) + EPSQ);  // 1/(sigmoid(max)+eps)
    }
    for (int n = blockIdx.x * 256 + tid; n < BQ * TQ; n += TAILBLOCKS * 256) {
        int b = n / TQ;
        float fa = 1.0f / (1.0f + __expf(-__ldcg(&g_fs[n])));
        out_fn[n] = fa * dnb[b];
    }
}

// ============================================================================
extern "C" void kernel_launch(void* const* d_in, const int* in_sizes, int n_in,
                              void* d_out, int out_size)
{
    const float* x         = (const float*)d_in[0];
    const float* log_gamma = (const float*)d_in[1];
    const float* diff_w    = (const float*)d_in[2];
    const float* diff_b    = (const float*)d_in[3];
    const float* la_w      = (const float*)d_in[4];
    const float* la_b      = (const float*)d_in[5];
    const float* mix_w     = (const float*)d_in[6];
    const float* g_w       = (const float*)d_in[7];
    const float* g_b       = (const float*)d_in[8];
    const float* fc_w      = (const float*)d_in[9];
    const float* fc_b      = (const float*)d_in[10];
    const float* fg_w      = (const float*)d_in[11];
    const float* fg_b      = (const float*)d_in[12];
    float* out = (float*)d_out;

    dim3 g1((TQ + 2047) / 2048, NBQ, BQ);     // 30 x 8 x 4
    k1_xp<<<g1, 256>>>(x, log_gamma, diff_w, diff_b);

    k_tail<<<TAILBLOCKS, 256>>>(la_w, la_b, mix_w, g_w, g_b,
                                fc_w, fc_b, fg_w, fg_b,
                                out, out + (size_t)BQ * TQ);
}

// round 4
// speedup vs baseline: 2.1514x; 1.1915x over previous
#include <cuda_runtime.h>
#include <math_constants.h>

// Problem dims (fixed instance)
#define BQ  4
#define FQ  256
#define TQ  60000
#define NBQ 8
#define FB  32
#define ND  5
#define NLA 11
#define NG  15
#define EPSQ 1e-8f

#define TT3 256    // tail tile (one output point per thread)
#define H3  19     // k2 halo: 5 (moving-avg) + 7 (gauss) + 7 (fuse gauss)

// ---- scratch (static device arrays; no allocation) ----
__device__ float g_xp[BQ * NBQ * TQ];   // pooled band envelopes  [B, NB, T]
__device__ float g_xg[BQ * TQ];         // smoothed flux (pre-norm)
__device__ float g_C[BQ * TQ];          // conv15(xg, fg_w), zero-padded
__device__ int   g_maxxg_bits[BQ];      // xg >= 0 -> plain int max works
__device__ int   g_maxC_key[BQ];        // monotone float->int keys
__device__ int   g_minC_key[BQ];

// monotone involution float <-> signed-int key (total order incl. negatives)
__device__ __forceinline__ int f2key(float v) {
    int u = __float_as_int(v);
    return (u >= 0) ? u : (u ^ 0x7FFFFFFF);
}
__device__ __forceinline__ float key2f(int k) {
    int u = (k >= 0) ? k : (k ^ 0x7FFFFFFF);
    return __int_as_float(u);
}

// ============================================================================
// K1: x [B,F,T] -> xp [B,NB,T]   (barrier-free, warp-autonomous, 8 t/lane)
// ============================================================================
__global__ __launch_bounds__(256) void k1_xp(
    const float* __restrict__ x,
    const float* __restrict__ log_gamma,
    const float* __restrict__ diff_w,
    const float* __restrict__ diff_b)
{
    const int tid = threadIdx.x;
    // fold scalar init here (k2/k3 read these only after k1 completes)
    if (blockIdx.x == 0 && blockIdx.y == 0 && blockIdx.z == 0 && tid < BQ) {
        g_maxxg_bits[tid] = 0;                     // xg >= 0
        g_maxC_key[tid]   = (int)0x80000000;       // -> -inf
        g_minC_key[tid]   = 0x7FFFFFFF;            // -> +inf
    }

    const int warp = tid >> 5;
    const int lane = tid & 31;
    const int band = blockIdx.y;
    const int b    = blockIdx.z;
    const int tbase = (blockIdx.x * 8 + warp) * 256 + 8 * lane;
    const bool inr  = (tbase < TQ);   // TQ % 8 == 0 -> full 8 in range

    const float gamma = __expf(log_gamma[band]);
    const float dw0 = diff_w[band * ND + 0];
    const float dw1 = diff_w[band * ND + 1];
    const float dw2 = diff_w[band * ND + 2];
    const float dw3 = diff_w[band * ND + 3];
    const float dw4 = diff_w[band * ND + 4];
    const float db  = diff_b[band];

    const float* xb = x + ((size_t)b * FQ + (size_t)band * FB) * TQ;

    float acc[8];
#pragma unroll
    for (int j = 0; j < 8; ++j) acc[j] = 0.f;

#pragma unroll 2
    for (int f = 0; f < FB; ++f) {
        const float* row = xb + (size_t)f * TQ;
        float e[12];   // log window l[-2 .. 9]
        if (inr) {
            float4 v0 = __ldcs((const float4*)(row + tbase));
            float4 v1 = __ldcs((const float4*)(row + tbase + 4));
            e[2]  = __logf(fmaf(gamma, v0.x, 1.0f));
            e[3]  = __logf(fmaf(gamma, v0.y, 1.0f));
            e[4]  = __logf(fmaf(gamma, v0.z, 1.0f));
            e[5]  = __logf(fmaf(gamma, v0.w, 1.0f));
            e[6]  = __logf(fmaf(gamma, v1.x, 1.0f));
            e[7]  = __logf(fmaf(gamma, v1.y, 1.0f));
            e[8]  = __logf(fmaf(gamma, v1.z, 1.0f));
            e[9]  = __logf(fmaf(gamma, v1.w, 1.0f));
        } else {
#pragma unroll
            for (int j = 2; j < 10; ++j) e[j] = 0.f;
        }
        // halo via shuffles (out-of-range lanes carry 0 == zero padding)
        e[0]  = __shfl_up_sync(0xffffffffu, e[8], 1);
        e[1]  = __shfl_up_sync(0xffffffffu, e[9], 1);
        e[10] = __shfl_down_sync(0xffffffffu, e[2], 1);
        e[11] = __shfl_down_sync(0xffffffffu, e[3], 1);
        if (lane == 0) {
            e[0] = (tbase >= 2) ? __logf(fmaf(gamma, row[tbase - 2], 1.0f)) : 0.f;
            e[1] = (tbase >= 1) ? __logf(fmaf(gamma, row[tbase - 1], 1.0f)) : 0.f;
        }
        if (lane == 31 && inr) {
            e[10] = (tbase + 8 < TQ) ? __logf(fmaf(gamma, row[tbase + 8], 1.0f)) : 0.f;
            e[11] = (tbase + 9 < TQ) ? __logf(fmaf(gamma, row[tbase + 9], 1.0f)) : 0.f;
        }
#pragma unroll
        for (int j = 0; j < 8; ++j) {
            float s = db;
            s = fmaf(dw0, e[j],     s);
            s = fmaf(dw1, e[j + 1], s);
            s = fmaf(dw2, e[j + 2], s);
            s = fmaf(dw3, e[j + 3], s);
            s = fmaf(dw4, e[j + 4], s);
            acc[j] += fmaxf(s, 0.f);
        }
    }

    if (inr) {
        float* out = g_xp + ((size_t)b * NBQ + band) * TQ + tbase;
        *(float4*)(out)     = make_float4(acc[0], acc[1], acc[2], acc[3]);
        *(float4*)(out + 4) = make_float4(acc[4], acc[5], acc[6], acc[7]);
    }
}

// ============================================================================
// K2: xp -> xg, C = conv15(xg, fg_w), + per-batch scalars (atomics)
//   xm = sum_band mix_w*(xp - (dwconv11(xp)+la_b))
//   xg = relu(conv15(xm, g_w) + g_b)   (0 outside [0,T))
//   C  = conv15(xg, fg_w)  (zero-padded)
//   atomics: max(xg); max/min of C over interior t in [7, T-7)
// ============================================================================
__global__ __launch_bounds__(256) void k2_xgC(
    const float* __restrict__ la_w, const float* __restrict__ la_b,
    const float* __restrict__ mix_w,
    const float* __restrict__ g_w,  const float* __restrict__ g_b,
    const float* __restrict__ fg_w)
{
    __shared__ float sxp[NBQ][TT3 + 2 * H3];   // 8 x 294
    __shared__ float sxm[TT3 + 28];            // 284
    __shared__ float sxg[TT3 + 14];            // 270
    __shared__ float wlaw[NBQ * NLA], wg[NG], wfg[NG], wlab[NBQ], wmw[NBQ];

    const int t0  = blockIdx.x * TT3;
    const int b   = blockIdx.y;
    const int tid = threadIdx.x;

    if (tid < NBQ * NLA) wlaw[tid] = la_w[tid];
    if (tid < NG)        { wg[tid] = g_w[tid]; wfg[tid] = fg_w[tid]; }
    if (tid < NBQ)       { wlab[tid] = la_b[tid]; wmw[tid] = mix_w[tid]; }

    const int W3 = TT3 + 2 * H3;  // 294
    for (int n = tid; n < NBQ * W3; n += 256) {
        int band = n / W3;
        int i    = n - band * W3;
        int t    = t0 - H3 + i;
        sxp[band][i] = (t >= 0 && t < TQ)
                     ? g_xp[((size_t)b * NBQ + band) * TQ + t] : 0.0f;
    }
    __syncthreads();

    // xm at t = t0-14+i, i in [0, TT3+28); xp center idx = i+5
    for (int i = tid; i < TT3 + 28; i += 256) {
        int t = t0 - 14 + i;
        float xm = 0.0f;
        if (t >= 0 && t < TQ) {
#pragma unroll
            for (int band = 0; band < NBQ; ++band) {
                float conv = wlab[band];
#pragma unroll
                for (int j = 0; j < NLA; ++j)
                    conv = fmaf(wlaw[band * NLA + j], sxp[band][i + j], conv);
                xm = fmaf(wmw[band], sxp[band][i + 5] - conv, xm);
            }
        }
        sxm[i] = xm;
    }
    __syncthreads();

    // xg at t = t0-7+j, j in [0, TT3+14)
    const float gb = g_b[0];
    for (int j = tid; j < TT3 + 14; j += 256) {
        int t = t0 - 7 + j;
        float v = 0.0f;
        if (t >= 0 && t < TQ) {
            float s = gb;
#pragma unroll
            for (int k = 0; k < NG; ++k) s = fmaf(wg[k], sxm[j + k], s);
            v = fmaxf(s, 0.0f);
        }
        sxg[j] = v;
    }
    __syncthreads();

    // outputs at t = t0 + tid
    float lmaxg = 0.0f;
    float lmaxC = -CUDART_INF_F, lminC = CUDART_INF_F;
    {
        int t = t0 + tid;
        if (t < TQ) {
            float xgv = sxg[tid + 7];
            g_xg[(size_t)b * TQ + t] = xgv;
            lmaxg = xgv;
            float C = 0.0f;
#pragma unroll
            for (int k = 0; k < NG; ++k) C = fmaf(wfg[k], sxg[tid + k], C);
            g_C[(size_t)b * TQ + t] = C;
            if (t >= 7 && t < TQ - 7) { lmaxC = C; lminC = C; }
        }
    }
    int kmax = f2key(lmaxC), kmin = f2key(lminC);
#pragma unroll
    for (int off = 16; off; off >>= 1) {
        lmaxg = fmaxf(lmaxg, __shfl_xor_sync(0xffffffffu, lmaxg, off));
        kmax  = max(kmax, __shfl_xor_sync(0xffffffffu, kmax, off));
        kmin  = min(kmin, __shfl_xor_sync(0xffffffffu, kmin, off));
    }
    if ((tid & 31) == 0) {
        atomicMax(&g_maxxg_bits[b], __float_as_int(lmaxg));  // xg >= 0
        atomicMax(&g_maxC_key[b], kmax);
        atomicMin(&g_minC_key[b], kmin);
    }
}

// ============================================================================
// K3: pure elementwise finale.
//   inv = 1/(max xg + eps); a = sum(fc_w)*inv
//   fs(t) = a*C(t) + cb*W(t) + fg_b   (W(t)=Wfull except 14 edge t per batch)
//   max fs from {interior bound via max/min C, 14 explicit edge values}
//   out1 = xg*inv ; out2 = sigmoid(fs)/(sigmoid(max fs)+eps)
// ============================================================================
__global__ __launch_bounds__(256) void k3_out(
    const float* __restrict__ fc_w, const float* __restrict__ fc_b,
    const float* __restrict__ fg_w, const float* __restrict__ fg_b,
    float* __restrict__ out_sf, float* __restrict__ out_fn)
{
    __shared__ float swfg[NG];
    __shared__ float sc[4];   // inv, a, dn, d_interior

    const int b   = blockIdx.y;
    const int tid = threadIdx.x;
    const int t   = blockIdx.x * 256 + tid;

    if (tid < NG) swfg[tid] = fg_w[tid];
    __syncthreads();

    if (tid == 0) {
        const float cb  = fc_b[0];
        const float fgb = fg_b[0];
        float S = fc_w[0] + fc_w[1] + fc_w[2] + fc_w[3];
        float maxxg = __int_as_float(g_maxxg_bits[b]);
        float inv = 1.0f / (maxxg + EPSQ);
        float a   = S * inv;
        float Wfull = 0.0f;
#pragma unroll
        for (int k = 0; k < NG; ++k) Wfull += swfg[k];
        float d_int = fmaf(cb, Wfull, fgb);
        float maxC = key2f(g_maxC_key[b]);
        float minC = key2f(g_minC_key[b]);
        float best = fmaf(a, (a >= 0.0f) ? maxC : minC, d_int);
        // 14 edge positions: t in [0,7) U [T-7, T)
#pragma unroll
        for (int e = 0; e < 14; ++e) {
            int tt = (e < 7) ? e : (TQ - 14 + e);
            float Wt = 0.0f;
#pragma unroll
            for (int k = 0; k < NG; ++k) {
                int p = tt - 7 + k;
                if (p >= 0 && p < TQ) Wt += swfg[k];
            }
            float fsv = fmaf(a, g_C[(size_t)b * TQ + tt], fmaf(cb, Wt, fgb));
            best = fmaxf(best, fsv);
        }
        float famax = 1.0f / (1.0f + __expf(-best));
        sc[0] = inv;
        sc[1] = a;
        sc[2] = 1.0f / (famax + EPSQ);
        sc[3] = d_int;
    }
    __syncthreads();

    if (t < TQ) {
        size_t n = (size_t)b * TQ + t;
        float sf = g_xg[n] * sc[0];
        out_sf[n] = sf;
        float d;
        if (t >= 7 && t < TQ - 7) {
            d = sc[3];
        } else {
            float Wt = 0.0f;
#pragma unroll
            for (int k = 0; k < NG; ++k) {
                int p = t - 7 + k;
                if (p >= 0 && p < TQ) Wt += swfg[k];
            }
            d = fmaf(fc_b[0], Wt, fg_b[0]);
        }
        float fs = fmaf(sc[1], g_C[n], d);
        out_fn[n] = sc[2] / (1.0f + __expf(-fs));
    }
}

// ============================================================================
extern "C" void kernel_launch(void* const* d_in, const int* in_sizes, int n_in,
                              void* d_out, int out_size)
{
    const float* x         = (const float*)d_in[0];
    const float* log_gamma = (const float*)d_in[1];
    const float* diff_w    = (const float*)d_in[2];
    const float* diff_b    = (const float*)d_in[3];
    const float* la_w      = (const float*)d_in[4];
    const float* la_b      = (const float*)d_in[5];
    const float* mix_w     = (const float*)d_in[6];
    const float* g_w       = (const float*)d_in[7];
    const float* g_b       = (const float*)d_in[8];
    const float* fc_w      = (const float*)d_in[9];
    const float* fc_b      = (const float*)d_in[10];
    const float* fg_w      = (const float*)d_in[11];
    const float* fg_b      = (const float*)d_in[12];
    float* out = (float*)d_out;

    dim3 g1((TQ + 2047) / 2048, NBQ, BQ);        // 30 x 8 x 4
    k1_xp<<<g1, 256>>>(x, log_gamma, diff_w, diff_b);

    dim3 g2((TQ + TT3 - 1) / TT3, BQ);           // 235 x 4
    k2_xgC<<<g2, 256>>>(la_w, la_b, mix_w, g_w, g_b, fg_w);
    k3_out<<<g2, 256>>>(fc_w, fc_b, fg_w, fg_b,
                        out, out + (size_t)BQ * TQ);
}

// round 5
// speedup vs baseline: 2.4326x; 1.1307x over previous
#include <cuda_runtime.h>
#include <math_constants.h>

// Problem dims (fixed instance)
#define BQ  4
#define FQ  256
#define TQ  60000
#define NBQ 8
#define FB  32
#define ND  5
#define NLA 11
#define NG  15
#define EPSQ 1e-8f

// K1 geometry: 16 elems/lane, 4 warps/block (128 thr), 2048 t per block
#define ELPL 16
#define K1W  4
#define K1B  (K1W * 32)
#define K1CH (K1W * ELPL * 32)   // 2048

#define TT3 256    // tail tile (one output point per thread)
#define H3  19     // k2 halo: 5 (moving-avg) + 7 (gauss) + 7 (fuse gauss)

// ---- scratch (static device arrays; no allocation) ----
__device__ float g_xp[BQ * NBQ * TQ];   // pooled band envelopes  [B, NB, T]
__device__ float g_xg[BQ * TQ];         // smoothed flux (pre-norm)
__device__ float g_C[BQ * TQ];          // conv15(xg, fg_w), zero-padded
__device__ int   g_maxxg_bits[BQ];      // xg >= 0 -> plain int max works
__device__ int   g_maxC_key[BQ];        // monotone float->int keys
__device__ int   g_minC_key[BQ];

// monotone involution float <-> signed-int key (total order incl. negatives)
__device__ __forceinline__ int f2key(float v) {
    int u = __float_as_int(v);
    return (u >= 0) ? u : (u ^ 0x7FFFFFFF);
}
__device__ __forceinline__ float key2f(int k) {
    int u = (k >= 0) ? k : (k ^ 0x7FFFFFFF);
    return __int_as_float(u);
}

// ============================================================================
// K1: x [B,F,T] -> xp [B,NB,T]
//   Warp owns a 512-t chunk of one (b, band); lane owns 16 consecutive t.
//   Per freq row: 4 streaming float4 LDGs, 16 logs, halo via 4 shuffles +
//   one merged edge fixup, 5-tap conv, relu, accumulate over 32 rows.
//   No smem, no barriers.
// ============================================================================
__global__ __launch_bounds__(K1B) void k1_xp(
    const float* __restrict__ x,
    const float* __restrict__ log_gamma,
    const float* __restrict__ diff_w,
    const float* __restrict__ diff_b)
{
    const int tid = threadIdx.x;
    // fold scalar init here (k2/k3 read these only after k1 completes)
    if (blockIdx.x == 0 && blockIdx.y == 0 && blockIdx.z == 0 && tid < BQ) {
        g_maxxg_bits[tid] = 0;                     // xg >= 0
        g_maxC_key[tid]   = (int)0x80000000;       // -> -inf
        g_minC_key[tid]   = 0x7FFFFFFF;            // -> +inf
    }

    const int warp = tid >> 5;
    const int lane = tid & 31;
    const int band = blockIdx.y;
    const int b    = blockIdx.z;
    const int tbase = blockIdx.x * K1CH + warp * (ELPL * 32) + ELPL * lane;
    const bool inr  = (tbase < TQ);   // TQ % 16 == 0 -> all 16 in range

    const float gamma = __expf(log_gamma[band]);
    const float dw0 = diff_w[band * ND + 0];
    const float dw1 = diff_w[band * ND + 1];
    const float dw2 = diff_w[band * ND + 2];
    const float dw3 = diff_w[band * ND + 3];
    const float dw4 = diff_w[band * ND + 4];
    const float db  = diff_b[band];

    const float* xb = x + ((size_t)b * FQ + (size_t)band * FB) * TQ;

    float acc[ELPL];
#pragma unroll
    for (int j = 0; j < ELPL; ++j) acc[j] = 0.f;

#pragma unroll 1
    for (int f = 0; f < FB; ++f) {
        const float* row = xb + (size_t)f * TQ;
        float e[ELPL + 4];   // log window, t in [tbase-2, tbase+ELPL+2)
        if (inr) {
            float4 v0 = __ldcs((const float4*)(row + tbase));
            float4 v1 = __ldcs((const float4*)(row + tbase + 4));
            float4 v2 = __ldcs((const float4*)(row + tbase + 8));
            float4 v3 = __ldcs((const float4*)(row + tbase + 12));
            e[2]  = __logf(fmaf(gamma, v0.x, 1.0f));
            e[3]  = __logf(fmaf(gamma, v0.y, 1.0f));
            e[4]  = __logf(fmaf(gamma, v0.z, 1.0f));
            e[5]  = __logf(fmaf(gamma, v0.w, 1.0f));
            e[6]  = __logf(fmaf(gamma, v1.x, 1.0f));
            e[7]  = __logf(fmaf(gamma, v1.y, 1.0f));
            e[8]  = __logf(fmaf(gamma, v1.z, 1.0f));
            e[9]  = __logf(fmaf(gamma, v1.w, 1.0f));
            e[10] = __logf(fmaf(gamma, v2.x, 1.0f));
            e[11] = __logf(fmaf(gamma, v2.y, 1.0f));
            e[12] = __logf(fmaf(gamma, v2.z, 1.0f));
            e[13] = __logf(fmaf(gamma, v2.w, 1.0f));
            e[14] = __logf(fmaf(gamma, v3.x, 1.0f));
            e[15] = __logf(fmaf(gamma, v3.y, 1.0f));
            e[16] = __logf(fmaf(gamma, v3.z, 1.0f));
            e[17] = __logf(fmaf(gamma, v3.w, 1.0f));
        } else {
#pragma unroll
            for (int j = 2; j < ELPL + 2; ++j) e[j] = 0.f;
        }
        // halo via shuffles (out-of-range lanes carry 0 == zero padding)
        e[0]        = __shfl_up_sync(0xffffffffu, e[ELPL], 1);
        e[1]        = __shfl_up_sync(0xffffffffu, e[ELPL + 1], 1);
        e[ELPL + 2] = __shfl_down_sync(0xffffffffu, e[2], 1);
        e[ELPL + 3] = __shfl_down_sync(0xffffffffu, e[3], 1);
        // merged edge fixup: one predicated region for lane 0 and lane 31
        if (lane == 0 || lane == 31) {
            int tb = (lane == 0) ? (tbase - 2) : (tbase + ELPL);
            float h0 = 0.f, h1 = 0.f;
            if (tb >= 0 && tb < TQ)
                h0 = __logf(fmaf(gamma, row[tb], 1.0f));
            if (tb + 1 >= 0 && tb + 1 < TQ)
                h1 = __logf(fmaf(gamma, row[tb + 1], 1.0f));
            if (lane == 0) { e[0] = h0; e[1] = h1; }
            else           { e[ELPL + 2] = h0; e[ELPL + 3] = h1; }
        }
#pragma unroll
        for (int j = 0; j < ELPL; ++j) {
            float s = db;
            s = fmaf(dw0, e[j],     s);
            s = fmaf(dw1, e[j + 1], s);
            s = fmaf(dw2, e[j + 2], s);
            s = fmaf(dw3, e[j + 3], s);
            s = fmaf(dw4, e[j + 4], s);
            acc[j] += fmaxf(s, 0.f);
        }
    }

    if (inr) {
        float* out = g_xp + ((size_t)b * NBQ + band) * TQ + tbase;
        *(float4*)(out)      = make_float4(acc[0],  acc[1],  acc[2],  acc[3]);
        *(float4*)(out + 4)  = make_float4(acc[4],  acc[5],  acc[6],  acc[7]);
        *(float4*)(out + 8)  = make_float4(acc[8],  acc[9],  acc[10], acc[11]);
        *(float4*)(out + 12) = make_float4(acc[12], acc[13], acc[14], acc[15]);
    }
}

// ============================================================================
// K2: xp -> xg, C = conv15(xg, fg_w), + per-batch scalars (atomics)
// ============================================================================
__global__ __launch_bounds__(256) void k2_xgC(
    const float* __restrict__ la_w, const float* __restrict__ la_b,
    const float* __restrict__ mix_w,
    const float* __restrict__ g_w,  const float* __restrict__ g_b,
    const float* __restrict__ fg_w)
{
    __shared__ float sxp[NBQ][TT3 + 2 * H3];   // 8 x 294
    __shared__ float sxm[TT3 + 28];            // 284
    __shared__ float sxg[TT3 + 14];            // 270
    __shared__ float wlaw[NBQ * NLA], wg[NG], wfg[NG], wlab[NBQ], wmw[NBQ];

    const int t0  = blockIdx.x * TT3;
    const int b   = blockIdx.y;
    const int tid = threadIdx.x;

    if (tid < NBQ * NLA) wlaw[tid] = la_w[tid];
    if (tid < NG)        { wg[tid] = g_w[tid]; wfg[tid] = fg_w[tid]; }
    if (tid < NBQ)       { wlab[tid] = la_b[tid]; wmw[tid] = mix_w[tid]; }

    const int W3 = TT3 + 2 * H3;  // 294
    for (int n = tid; n < NBQ * W3; n += 256) {
        int band = n / W3;
        int i    = n - band * W3;
        int t    = t0 - H3 + i;
        sxp[band][i] = (t >= 0 && t < TQ)
                     ? g_xp[((size_t)b * NBQ + band) * TQ + t] : 0.0f;
    }
    __syncthreads();

    // xm at t = t0-14+i, i in [0, TT3+28); xp center idx = i+5
    for (int i = tid; i < TT3 + 28; i += 256) {
        int t = t0 - 14 + i;
        float xm = 0.0f;
        if (t >= 0 && t < TQ) {
#pragma unroll
            for (int band = 0; band < NBQ; ++band) {
                float conv = wlab[band];
#pragma unroll
                for (int j = 0; j < NLA; ++j)
                    conv = fmaf(wlaw[band * NLA + j], sxp[band][i + j], conv);
                xm = fmaf(wmw[band], sxp[band][i + 5] - conv, xm);
            }
        }
        sxm[i] = xm;
    }
    __syncthreads();

    // xg at t = t0-7+j, j in [0, TT3+14)
    const float gb = g_b[0];
    for (int j = tid; j < TT3 + 14; j += 256) {
        int t = t0 - 7 + j;
        float v = 0.0f;
        if (t >= 0 && t < TQ) {
            float s = gb;
#pragma unroll
            for (int k = 0; k < NG; ++k) s = fmaf(wg[k], sxm[j + k], s);
            v = fmaxf(s, 0.0f);
        }
        sxg[j] = v;
    }
    __syncthreads();

    // outputs at t = t0 + tid
    float lmaxg = 0.0f;
    float lmaxC = -CUDART_INF_F, lminC = CUDART_INF_F;
    {
        int t = t0 + tid;
        if (t < TQ) {
            float xgv = sxg[tid + 7];
            g_xg[(size_t)b * TQ + t] = xgv;
            lmaxg = xgv;
            float C = 0.0f;
#pragma unroll
            for (int k = 0; k < NG; ++k) C = fmaf(wfg[k], sxg[tid + k], C);
            g_C[(size_t)b * TQ + t] = C;
            if (t >= 7 && t < TQ - 7) { lmaxC = C; lminC = C; }
        }
    }
    int kmax = f2key(lmaxC), kmin = f2key(lminC);
#pragma unroll
    for (int off = 16; off; off >>= 1) {
        lmaxg = fmaxf(lmaxg, __shfl_xor_sync(0xffffffffu, lmaxg, off));
        kmax  = max(kmax, __shfl_xor_sync(0xffffffffu, kmax, off));
        kmin  = min(kmin, __shfl_xor_sync(0xffffffffu, kmin, off));
    }
    if ((tid & 31) == 0) {
        atomicMax(&g_maxxg_bits[b], __float_as_int(lmaxg));  // xg >= 0
        atomicMax(&g_maxC_key[b], kmax);
        atomicMin(&g_minC_key[b], kmin);
    }
}

// ============================================================================
// K3: pure elementwise finale.
//   inv = 1/(max xg + eps); a = sum(fc_w)*inv
//   fs(t) = a*C(t) + cb*W(t) + fg_b   (W(t)=Wfull except 14 edge t per batch)
//   max fs from {interior bound via max/min C, 14 explicit edge values}
//   out1 = xg*inv ; out2 = sigmoid(fs)/(sigmoid(max fs)+eps)
// ============================================================================
__global__ __launch_bounds__(256) void k3_out(
    const float* __restrict__ fc_w, const float* __restrict__ fc_b,
    const float* __restrict__ fg_w, const float* __restrict__ fg_b,
    float* __restrict__ out_sf, float* __restrict__ out_fn)
{
    __shared__ float swfg[NG];
    __shared__ float sc[4];   // inv, a, dn, d_interior

    const int b   = blockIdx.y;
    const int tid = threadIdx.x;
    const int t   = blockIdx.x * 256 + tid;

    if (tid < NG) swfg[tid] = fg_w[tid];
    __syncthreads();

    if (tid == 0) {
        const float cb  = fc_b[0];
        const float fgb = fg_b[0];
        float S = fc_w[0] + fc_w[1] + fc_w[2] + fc_w[3];
        float maxxg = __int_as_float(g_maxxg_bits[b]);
        float inv = 1.0f / (maxxg + EPSQ);
        float a   = S * inv;
        float Wfull = 0.0f;
#pragma unroll
        for (int k = 0; k < NG; ++k) Wfull += swfg[k];
        float d_int = fmaf(cb, Wfull, fgb);
        float maxC = key2f(g_maxC_key[b]);
        float minC = key2f(g_minC_key[b]);
        float best = fmaf(a, (a >= 0.0f) ? maxC : minC, d_int);
        // 14 edge positions: t in [0,7) U [T-7, T)
#pragma unroll
        for (int e = 0; e < 14; ++e) {
            int tt = (e < 7) ? e : (TQ - 14 + e);
            float Wt = 0.0f;
#pragma unroll
            for (int k = 0; k < NG; ++k) {
                int p = tt - 7 + k;
                if (p >= 0 && p < TQ) Wt += swfg[k];
            }
            float fsv = fmaf(a, g_C[(size_t)b * TQ + tt], fmaf(cb, Wt, fgb));
            best = fmaxf(best, fsv);
        }
        float famax = 1.0f / (1.0f + __expf(-best));
        sc[0] = inv;
        sc[1] = a;
        sc[2] = 1.0f / (famax + EPSQ);
        sc[3] = d_int;
    }
    __syncthreads();

    if (t < TQ) {
        size_t n = (size_t)b * TQ + t;
        float sf = g_xg[n] * sc[0];
        out_sf[n] = sf;
        float d;
        if (t >= 7 && t < TQ - 7) {
            d = sc[3];
        } else {
            float Wt = 0.0f;
#pragma unroll
            for (int k = 0; k < NG; ++k) {
                int p = t - 7 + k;
                if (p >= 0 && p < TQ) Wt += swfg[k];
            }
            d = fmaf(fc_b[0], Wt, fg_b[0]);
        }
        float fs = fmaf(sc[1], g_C[n], d);
        out_fn[n] = sc[2] / (1.0f + __expf(-fs));
    }
}

// ============================================================================
extern "C" void kernel_launch(void* const* d_in, const int* in_sizes, int n_in,
                              void* d_out, int out_size)
{
    const float* x         = (const float*)d_in[0];
    const float* log_gamma = (const float*)d_in[1];
    const float* diff_w    = (const float*)d_in[2];
    const float* diff_b    = (const float*)d_in[3];
    const float* la_w      = (const float*)d_in[4];
    const float* la_b      = (const float*)d_in[5];
    const float* mix_w     = (const float*)d_in[6];
    const float* g_w       = (const float*)d_in[7];
    const float* g_b       = (const float*)d_in[8];
    const float* fc_w      = (const float*)d_in[9];
    const float* fc_b      = (const float*)d_in[10];
    const float* fg_w      = (const float*)d_in[11];
    const float* fg_b      = (const float*)d_in[12];
    float* out = (float*)d_out;

    dim3 g1((TQ + K1CH - 1) / K1CH, NBQ, BQ);    // 30 x 8 x 4
    k1_xp<<<g1, K1B>>>(x, log_gamma, diff_w, diff_b);

    dim3 g2((TQ + TT3 - 1) / TT3, BQ);           // 235 x 4
    k2_xgC<<<g2, 256>>>(la_w, la_b, mix_w, g_w, g_b, fg_w);
    k3_out<<<g2, 256>>>(fc_w, fc_b, fg_w, fg_b,
                        out, out + (size_t)BQ * TQ);
}

// round 6
// speedup vs baseline: 2.5481x; 1.0475x over previous
#include <cuda_runtime.h>
#include <math_constants.h>

// Problem dims (fixed instance)
#define BQ  4
#define FQ  256
#define TQ  60000
#define NBQ 8
#define FB  32
#define ND  5
#define NLA 11
#define NG  15
#define EPSQ 1e-8f
#define LN2F 0.6931471805599453f

// K1 geometry: block = 128 thr (4 warps) owns a 512-t span; warps split the
// 32 freq rows 8 each; smem reduction combines partial band sums.
#define ELPL  16
#define K1B   128
#define K1SPAN 512
#define ROWS_PER_WARP (FB / 4)   // 8

#define TT3 256    // tail tile (one output point per thread)
#define H3  19     // k2 halo: 5 (moving-avg) + 7 (gauss) + 7 (fuse gauss)

// ---- scratch (static device arrays; no allocation) ----
__device__ float g_xp[BQ * NBQ * TQ];   // pooled band envelopes  [B, NB, T]
__device__ float g_xg[BQ * TQ];         // smoothed flux (pre-norm)
__device__ float g_C[BQ * TQ];          // conv15(xg, fg_w), zero-padded
__device__ int   g_maxxg_bits[BQ];      // xg >= 0 -> plain int max works
__device__ int   g_maxC_key[BQ];        // monotone float->int keys
__device__ int   g_minC_key[BQ];

// monotone involution float <-> signed-int key (total order incl. negatives)
__device__ __forceinline__ int f2key(float v) {
    int u = __float_as_int(v);
    return (u >= 0) ? u : (u ^ 0x7FFFFFFF);
}
__device__ __forceinline__ float key2f(int k) {
    int u = (k >= 0) ? k : (k ^ 0x7FFFFFFF);
    return __int_as_float(u);
}

// ============================================================================
// K1: x [B,F,T] -> xp [B,NB,T]
//   Block (128 thr) owns a 512-t span of one (b, band). Warp w accumulates
//   freq rows [8w, 8w+8). Lane owns 16 consecutive t. Per row: 4 streaming
//   float4 LDGs, 16 log2s (ln2 folded into conv weights), halo via 4
//   shuffles + merged edge fixup, 5-tap conv, relu. Partial sums over the
//   4 warps combined through smem at the end.
// ============================================================================
__global__ __launch_bounds__(K1B) void k1_xp(
    const float* __restrict__ x,
    const float* __restrict__ log_gamma,
    const float* __restrict__ diff_w,
    const float* __restrict__ diff_b)
{
    __shared__ float sred[4][K1SPAN];

    const int tid = threadIdx.x;
    // fold scalar init here (k2/k3 read these only after k1 completes)
    if (blockIdx.x == 0 && blockIdx.y == 0 && blockIdx.z == 0 && tid < BQ) {
        g_maxxg_bits[tid] = 0;                     // xg >= 0
        g_maxC_key[tid]   = (int)0x80000000;       // -> -inf
        g_minC_key[tid]   = 0x7FFFFFFF;            // -> +inf
    }

    const int warp = tid >> 5;
    const int lane = tid & 31;
    const int band = blockIdx.y;
    const int b    = blockIdx.z;
    const int tbase = blockIdx.x * K1SPAN + ELPL * lane;   // same span all warps
    const bool inr  = (tbase < TQ);   // TQ % 16 == 0 -> all 16 in range

    const float gamma = __expf(log_gamma[band]);
    // ln2 folded into the diff taps: conv(ln y) = sum (dw*ln2) * log2(y)
    const float dw0 = diff_w[band * ND + 0] * LN2F;
    const float dw1 = diff_w[band * ND + 1] * LN2F;
    const float dw2 = diff_w[band * ND + 2] * LN2F;
    const float dw3 = diff_w[band * ND + 3] * LN2F;
    const float dw4 = diff_w[band * ND + 4] * LN2F;
    const float db  = diff_b[band];

    const float* xb = x + ((size_t)b * FQ + (size_t)band * FB
                           + (size_t)warp * ROWS_PER_WARP) * TQ;

    float acc[ELPL];
#pragma unroll
    for (int j = 0; j < ELPL; ++j) acc[j] = 0.f;

#pragma unroll 1
    for (int f = 0; f < ROWS_PER_WARP; ++f) {
        const float* row = xb + (size_t)f * TQ;
        float e[ELPL + 4];   // log2 window, t in [tbase-2, tbase+ELPL+2)
        if (inr) {
            float4 v0 = __ldcs((const float4*)(row + tbase));
            float4 v1 = __ldcs((const float4*)(row + tbase + 4));
            float4 v2 = __ldcs((const float4*)(row + tbase + 8));
            float4 v3 = __ldcs((const float4*)(row + tbase + 12));
            e[2]  = __log2f(fmaf(gamma, v0.x, 1.0f));
            e[3]  = __log2f(fmaf(gamma, v0.y, 1.0f));
            e[4]  = __log2f(fmaf(gamma, v0.z, 1.0f));
            e[5]  = __log2f(fmaf(gamma, v0.w, 1.0f));
            e[6]  = __log2f(fmaf(gamma, v1.x, 1.0f));
            e[7]  = __log2f(fmaf(gamma, v1.y, 1.0f));
            e[8]  = __log2f(fmaf(gamma, v1.z, 1.0f));
            e[9]  = __log2f(fmaf(gamma, v1.w, 1.0f));
            e[10] = __log2f(fmaf(gamma, v2.x, 1.0f));
            e[11] = __log2f(fmaf(gamma, v2.y, 1.0f));
            e[12] = __log2f(fmaf(gamma, v2.z, 1.0f));
            e[13] = __log2f(fmaf(gamma, v2.w, 1.0f));
            e[14] = __log2f(fmaf(gamma, v3.x, 1.0f));
            e[15] = __log2f(fmaf(gamma, v3.y, 1.0f));
            e[16] = __log2f(fmaf(gamma, v3.z, 1.0f));
            e[17] = __log2f(fmaf(gamma, v3.w, 1.0f));
        } else {
#pragma unroll
            for (int j = 2; j < ELPL + 2; ++j) e[j] = 0.f;
        }
        // halo via shuffles (out-of-range lanes carry 0 == zero padding)
        e[0]        = __shfl_up_sync(0xffffffffu, e[ELPL], 1);
        e[1]        = __shfl_up_sync(0xffffffffu, e[ELPL + 1], 1);
        e[ELPL + 2] = __shfl_down_sync(0xffffffffu, e[2], 1);
        e[ELPL + 3] = __shfl_down_sync(0xffffffffu, e[3], 1);
        // merged edge fixup: one predicated region for lane 0 and lane 31
        if (lane == 0 || lane == 31) {
            int tb = (lane == 0) ? (tbase - 2) : (tbase + ELPL);
            float h0 = 0.f, h1 = 0.f;
            if (tb >= 0 && tb < TQ)
                h0 = __log2f(fmaf(gamma, row[tb], 1.0f));
            if (tb + 1 >= 0 && tb + 1 < TQ)
                h1 = __log2f(fmaf(gamma, row[tb + 1], 1.0f));
            if (lane == 0) { e[0] = h0; e[1] = h1; }
            else           { e[ELPL + 2] = h0; e[ELPL + 3] = h1; }
        }
#pragma unroll
        for (int j = 0; j < ELPL; ++j) {
            float s = db;
            s = fmaf(dw0, e[j],     s);
            s = fmaf(dw1, e[j + 1], s);
            s = fmaf(dw2, e[j + 2], s);
            s = fmaf(dw3, e[j + 3], s);
            s = fmaf(dw4, e[j + 4], s);
            acc[j] += fmaxf(s, 0.f);
        }
    }

    // combine the 4 warps' partial sums through smem
#pragma unroll
    for (int q = 0; q < 4; ++q)
        *(float4*)&sred[warp][ELPL * lane + 4 * q] =
            make_float4(acc[4*q], acc[4*q+1], acc[4*q+2], acc[4*q+3]);
    __syncthreads();

    {
        int i0 = 4 * tid;                      // 0..508
        int t  = blockIdx.x * K1SPAN + i0;
        if (t < TQ) {                          // TQ%4==0 -> whole float4 in range
            float4 r0 = *(const float4*)&sred[0][i0];
            float4 r1 = *(const float4*)&sred[1][i0];
            float4 r2 = *(const float4*)&sred[2][i0];
            float4 r3 = *(const float4*)&sred[3][i0];
            float4 o;
            o.x = (r0.x + r1.x) + (r2.x + r3.x);
            o.y = (r0.y + r1.y) + (r2.y + r3.y);
            o.z = (r0.z + r1.z) + (r2.z + r3.z);
            o.w = (r0.w + r1.w) + (r2.w + r3.w);
            *(float4*)&g_xp[((size_t)b * NBQ + band) * TQ + t] = o;
        }
    }
}

// ============================================================================
// K2: xp -> xg, C = conv15(xg, fg_w), + per-batch scalars (atomics)
// ============================================================================
__global__ __launch_bounds__(256) void k2_xgC(
    const float* __restrict__ la_w, const float* __restrict__ la_b,
    const float* __restrict__ mix_w,
    const float* __restrict__ g_w,  const float* __restrict__ g_b,
    const float* __restrict__ fg_w)
{
    __shared__ float sxp[NBQ][TT3 + 2 * H3];   // 8 x 294
    __shared__ float sxm[TT3 + 28];            // 284
    __shared__ float sxg[TT3 + 14];            // 270
    __shared__ float wlaw[NBQ * NLA], wg[NG], wfg[NG], wlab[NBQ], wmw[NBQ];

    const int t0  = blockIdx.x * TT3;
    const int b   = blockIdx.y;
    const int tid = threadIdx.x;

    if (tid < NBQ * NLA) wlaw[tid] = la_w[tid];
    if (tid < NG)        { wg[tid] = g_w[tid]; wfg[tid] = fg_w[tid]; }
    if (tid < NBQ)       { wlab[tid] = la_b[tid]; wmw[tid] = mix_w[tid]; }

    const int W3 = TT3 + 2 * H3;  // 294
    for (int n = tid; n < NBQ * W3; n += 256) {
        int band = n / W3;
        int i    = n - band * W3;
        int t    = t0 - H3 + i;
        sxp[band][i] = (t >= 0 && t < TQ)
                     ? g_xp[((size_t)b * NBQ + band) * TQ + t] : 0.0f;
    }
    __syncthreads();

    // xm at t = t0-14+i, i in [0, TT3+28); xp center idx = i+5
    for (int i = tid; i < TT3 + 28; i += 256) {
        int t = t0 - 14 + i;
        float xm = 0.0f;
        if (t >= 0 && t < TQ) {
#pragma unroll
            for (int band = 0; band < NBQ; ++band) {
                float conv = wlab[band];
#pragma unroll
                for (int j = 0; j < NLA; ++j)
                    conv = fmaf(wlaw[band * NLA + j], sxp[band][i + j], conv);
                xm = fmaf(wmw[band], sxp[band][i + 5] - conv, xm);
            }
        }
        sxm[i] = xm;
    }
    __syncthreads();

    // xg at t = t0-7+j, j in [0, TT3+14)
    const float gb = g_b[0];
    for (int j = tid; j < TT3 + 14; j += 256) {
        int t = t0 - 7 + j;
        float v = 0.0f;
        if (t >= 0 && t < TQ) {
            float s = gb;
#pragma unroll
            for (int k = 0; k < NG; ++k) s = fmaf(wg[k], sxm[j + k], s);
            v = fmaxf(s, 0.0f);
        }
        sxg[j] = v;
    }
    __syncthreads();

    // outputs at t = t0 + tid
    float lmaxg = 0.0f;
    float lmaxC = -CUDART_INF_F, lminC = CUDART_INF_F;
    {
        int t = t0 + tid;
        if (t < TQ) {
            float xgv = sxg[tid + 7];
            g_xg[(size_t)b * TQ + t] = xgv;
            lmaxg = xgv;
            float C = 0.0f;
#pragma unroll
            for (int k = 0; k < NG; ++k) C = fmaf(wfg[k], sxg[tid + k], C);
            g_C[(size_t)b * TQ + t] = C;
            if (t >= 7 && t < TQ - 7) { lmaxC = C; lminC = C; }
        }
    }
    int kmax = f2key(lmaxC), kmin = f2key(lminC);
#pragma unroll
    for (int off = 16; off; off >>= 1) {
        lmaxg = fmaxf(lmaxg, __shfl_xor_sync(0xffffffffu, lmaxg, off));
        kmax  = max(kmax, __shfl_xor_sync(0xffffffffu, kmax, off));
        kmin  = min(kmin, __shfl_xor_sync(0xffffffffu, kmin, off));
    }
    if ((tid & 31) == 0) {
        atomicMax(&g_maxxg_bits[b], __float_as_int(lmaxg));  // xg >= 0
        atomicMax(&g_maxC_key[b], kmax);
        atomicMin(&g_minC_key[b], kmin);
    }
}

// ============================================================================
// K3: pure elementwise finale.
// ============================================================================
__global__ __launch_bounds__(256) void k3_out(
    const float* __restrict__ fc_w, const float* __restrict__ fc_b,
    const float* __restrict__ fg_w, const float* __restrict__ fg_b,
    float* __restrict__ out_sf, float* __restrict__ out_fn)
{
    __shared__ float swfg[NG];
    __shared__ float sc[4];   // inv, a, dn, d_interior

    const int b   = blockIdx.y;
    const int tid = threadIdx.x;
    const int t   = blockIdx.x * 256 + tid;

    if (tid < NG) swfg[tid] = fg_w[tid];
    __syncthreads();

    if (tid == 0) {
        const float cb  = fc_b[0];
        const float fgb = fg_b[0];
        float S = fc_w[0] + fc_w[1] + fc_w[2] + fc_w[3];
        float maxxg = __int_as_float(g_maxxg_bits[b]);
        float inv = 1.0f / (maxxg + EPSQ);
        float a   = S * inv;
        float Wfull = 0.0f;
#pragma unroll
        for (int k = 0; k < NG; ++k) Wfull += swfg[k];
        float d_int = fmaf(cb, Wfull, fgb);
        float maxC = key2f(g_maxC_key[b]);
        float minC = key2f(g_minC_key[b]);
        float best = fmaf(a, (a >= 0.0f) ? maxC : minC, d_int);
        // 14 edge positions: t in [0,7) U [T-7, T)
#pragma unroll
        for (int e = 0; e < 14; ++e) {
            int tt = (e < 7) ? e : (TQ - 14 + e);
            float Wt = 0.0f;
#pragma unroll
            for (int k = 0; k < NG; ++k) {
                int p = tt - 7 + k;
                if (p >= 0 && p < TQ) Wt += swfg[k];
            }
            float fsv = fmaf(a, g_C[(size_t)b * TQ + tt], fmaf(cb, Wt, fgb));
            best = fmaxf(best, fsv);
        }
        float famax = 1.0f / (1.0f + __expf(-best));
        sc[0] = inv;
        sc[1] = a;
        sc[2] = 1.0f / (famax + EPSQ);
        sc[3] = d_int;
    }
    __syncthreads();

    if (t < TQ) {
        size_t n = (size_t)b * TQ + t;
        float sf = g_xg[n] * sc[0];
        out_sf[n] = sf;
        float d;
        if (t >= 7 && t < TQ - 7) {
            d = sc[3];
        } else {
            float Wt = 0.0f;
#pragma unroll
            for (int k = 0; k < NG; ++k) {
                int p = t - 7 + k;
                if (p >= 0 && p < TQ) Wt += swfg[k];
            }
            d = fmaf(fc_b[0], Wt, fg_b[0]);
        }
        float fs = fmaf(sc[1], g_C[n], d);
        out_fn[n] = sc[2] / (1.0f + __expf(-fs));
    }
}

// ============================================================================
extern "C" void kernel_launch(void* const* d_in, const int* in_sizes, int n_in,
                              void* d_out, int out_size)
{
    const float* x         = (const float*)d_in[0];
    const float* log_gamma = (const float*)d_in[1];
    const float* diff_w    = (const float*)d_in[2];
    const float* diff_b    = (const float*)d_in[3];
    const float* la_w      = (const float*)d_in[4];
    const float* la_b      = (const float*)d_in[5];
    const float* mix_w     = (const float*)d_in[6];
    const float* g_w       = (const float*)d_in[7];
    const float* g_b       = (const float*)d_in[8];
    const float* fc_w      = (const float*)d_in[9];
    const float* fc_b      = (const float*)d_in[10];
    const float* fg_w      = (const float*)d_in[11];
    const float* fg_b      = (const float*)d_in[12];
    float* out = (float*)d_out;

    dim3 g1((TQ + K1SPAN - 1) / K1SPAN, NBQ, BQ);  // 118 x 8 x 4
    k1_xp<<<g1, K1B>>>(x, log_gamma, diff_w, diff_b);

    dim3 g2((TQ + TT3 - 1) / TT3, BQ);             // 235 x 4
    k2_xgC<<<g2, 256>>>(la_w, la_b, mix_w, g_w, g_b, fg_w);
    k3_out<<<g2, 256>>>(fc_w, fc_b, fg_w, fg_b,
                        out, out + (size_t)BQ * TQ);
}